// round 9
// baseline (speedup 1.0000x reference)
#include <cuda_runtime.h>

// LIIF_3d: identity-gather + 6-layer SIREN MLP, 3 time replicas.
// feat [2,64,192,320] f32; times[3]; w0[64,65] b0[64]; w1[64,64] b1;
// w2[256,64] b2; w3[256,256] b3; w4[256,256] b4; w5[64,256] b5.
// out [3,2,64,192,320] f32.

#define HWSZ   61440      // 192*320
#define NBATCH 2
#define AST    68         // activation row stride (floats), padded
#define WST    68         // weight-chunk row stride
#define KC     16         // K-chunk
#define NTHR   256

struct P6 {
    const float* w[6];
    const float* b[6];
};

// One dense layer: Aout[o][r] = act( sum_k W[o][k]*Ain[k][r] + bias_eff[o] )
// Ain: smem [K][AST]; Aout: smem [O][AST]; Ws: smem [KC][WST].
// tW: optional column W0[:,64] (stride Kstride) folded as bias += tval*tW[o*Kstride].
__device__ __forceinline__ void layer_gemm(
    const float* __restrict__ Wg, int Kstride,
    const float* __restrict__ bg,
    const float* __restrict__ tW, float tval,
    const float* __restrict__ Ain, float* __restrict__ Aout,
    float* __restrict__ Ws,
    int K, int O, bool act, int tid)
{
    const int tx = tid & 15;        // col group: cols tx*4..tx*4+3
    const int ty = tid >> 4;        // row group: rows ty*4..ty*4+3
    const int o_l = ty;             // weight-load o lane (0..15)
    const int k_l = tx;             // weight-load k lane (0..15)

    for (int ot = 0; ot < O; ot += 64) {
        float acc[4][4] = {};
        float wreg[4];
        // prefetch first chunk of this column tile
        #pragma unroll
        for (int p = 0; p < 4; p++)
            wreg[p] = Wg[(size_t)(ot + o_l + p * 16) * Kstride + k_l];

        for (int kc = 0; kc < K; kc += KC) {
            __syncthreads();                    // prev readers of Ws done
            #pragma unroll
            for (int p = 0; p < 4; p++)
                Ws[k_l * WST + o_l + p * 16] = wreg[p];
            __syncthreads();                    // Ws chunk visible

            const int kn = kc + KC;
            if (kn < K) {                       // overlap next-chunk LDG with compute
                #pragma unroll
                for (int p = 0; p < 4; p++)
                    wreg[p] = Wg[(size_t)(ot + o_l + p * 16) * Kstride + kn + k_l];
            }

            #pragma unroll
            for (int k = 0; k < KC; k++) {
                float4 a = *(const float4*)(Ain + (kc + k) * AST + (ty << 2));
                float4 w = *(const float4*)(Ws + k * WST + (tx << 2));
                acc[0][0] += a.x * w.x; acc[0][1] += a.x * w.y;
                acc[0][2] += a.x * w.z; acc[0][3] += a.x * w.w;
                acc[1][0] += a.y * w.x; acc[1][1] += a.y * w.y;
                acc[1][2] += a.y * w.z; acc[1][3] += a.y * w.w;
                acc[2][0] += a.z * w.x; acc[2][1] += a.z * w.y;
                acc[2][2] += a.z * w.z; acc[2][3] += a.z * w.w;
                acc[3][0] += a.w * w.x; acc[3][1] += a.w * w.y;
                acc[3][2] += a.w * w.z; acc[3][3] += a.w * w.w;
            }
        }

        // epilogue: bias (+ folded time term), sin(30x), transpose-store to Aout[o][r]
        #pragma unroll
        for (int j = 0; j < 4; j++) {
            int o = ot + (tx << 2) + j;
            float bb = bg[o];
            if (tW) bb += tval * tW[(size_t)o * Kstride];
            float4 v;
            v.x = acc[0][j] + bb;
            v.y = acc[1][j] + bb;
            v.z = acc[2][j] + bb;
            v.w = acc[3][j] + bb;
            if (act) {
                v.x = __sinf(30.0f * v.x);
                v.y = __sinf(30.0f * v.y);
                v.z = __sinf(30.0f * v.z);
                v.w = __sinf(30.0f * v.w);
            }
            *(float4*)(Aout + o * AST + (ty << 2)) = v;
        }
    }
}

extern __shared__ float s_dyn[];

__global__ void __launch_bounds__(NTHR, 1)
siren_kernel(const float* __restrict__ feat,
             const float* __restrict__ times,
             P6 p,
             float* __restrict__ out)
{
    float* A0 = s_dyn;                    // [256][AST]
    float* A1 = s_dyn + 256 * AST;        // [256][AST]
    float* Ws = s_dyn + 2 * 256 * AST;    // [KC][WST]

    const int tid  = threadIdx.x;
    const int tile = blockIdx.x;          // 0..1919
    const int t    = blockIdx.y;          // 0..2
    const int bimg = tile / (HWSZ / 64);  // 0..1
    const int pix0 = (tile % (HWSZ / 64)) * 64;

    // Load 64x64 feat tile (identity gather): A0[c][r] = feat[b][c][pix0+r]
    const float* fb = feat + (size_t)bimg * 64 * HWSZ + pix0;
    #pragma unroll 4
    for (int i = tid; i < 64 * 64; i += NTHR) {
        int c = i >> 6, r = i & 63;
        A0[c * AST + r] = fb[(size_t)c * HWSZ + r];
    }
    const float tval = __ldg(times + t);

    // L0: 64(+t)->64 sin     (t column folded into bias)
    layer_gemm(p.w[0], 65,  p.b[0], p.w[0] + 64, tval, A0, A1, Ws,  64,  64, true,  tid);
    // L1: 64->64 sin
    layer_gemm(p.w[1], 64,  p.b[1], nullptr, 0.f,      A1, A0, Ws,  64,  64, true,  tid);
    // L2: 64->256 sin
    layer_gemm(p.w[2], 64,  p.b[2], nullptr, 0.f,      A0, A1, Ws,  64, 256, true,  tid);
    // L3: 256->256 sin
    layer_gemm(p.w[3], 256, p.b[3], nullptr, 0.f,      A1, A0, Ws, 256, 256, true,  tid);
    // L4: 256->256 sin
    layer_gemm(p.w[4], 256, p.b[4], nullptr, 0.f,      A0, A1, Ws, 256, 256, true,  tid);
    // L5: 256->64 linear
    layer_gemm(p.w[5], 256, p.b[5], nullptr, 0.f,      A1, A0, Ws, 256,  64, false, tid);

    __syncthreads();

    // Store: out[t][b][c][pix0+r] = A0[c][r]  (coalesced per channel row)
    float* ob = out + ((size_t)t * NBATCH + bimg) * 64 * HWSZ + pix0;
    #pragma unroll 4
    for (int i = tid; i < 64 * 64; i += NTHR) {
        int c = i >> 6, r = i & 63;
        ob[(size_t)c * HWSZ + r] = A0[c * AST + r];
    }
}

extern "C" void kernel_launch(void* const* d_in, const int* in_sizes, int n_in,
                              void* d_out, int out_size)
{
    const float* feat  = (const float*)d_in[0];
    const float* times = (const float*)d_in[1];
    P6 p;
    for (int i = 0; i < 6; i++) {
        p.w[i] = (const float*)d_in[2 + 2 * i];
        p.b[i] = (const float*)d_in[3 + 2 * i];
    }
    float* out = (float*)d_out;

    const int smem_bytes = (2 * 256 * AST + KC * WST) * (int)sizeof(float); // 143,616 B
    cudaFuncSetAttribute(siren_kernel, cudaFuncAttributeMaxDynamicSharedMemorySize,
                         smem_bytes);

    dim3 grid((NBATCH * HWSZ) / 64, 3);   // (1920, 3)
    siren_kernel<<<grid, NTHR, smem_bytes>>>(feat, times, p, out);
}

// round 10
// speedup vs baseline: 1.0036x; 1.0036x over previous
#include <cuda_runtime.h>

// LIIF_3d: identity-gather + 6-layer SIREN MLP, 3 time replicas.
// feat [2,64,192,320] f32; times[3]; w0[64,65] b0[64]; w1[64,64] b1;
// w2[256,64] b2; w3[256,256] b3; w4[256,256] b4; w5[64,256] b5.
// out [3,2,64,192,320] f32.

#define HWSZ   61440      // 192*320
#define NBATCH 2
#define AST    68         // activation row stride (floats), padded
#define WST    68         // weight-chunk row stride
#define KC     16         // K-chunk
#define NTHR   256

struct P6 {
    const float* w[6];
    const float* b[6];
};

// One dense layer: Aout[o][r] = act( sum_k W[o][k]*Ain[k][r] + bias_eff[o] )
// Ain: smem [K][AST]; Aout: smem [O][AST]; Ws: smem [KC][WST].
// tW: optional column W0[:,64] (stride Kstride) folded as bias += tval*tW[o*Kstride].
__device__ __forceinline__ void layer_gemm(
    const float* __restrict__ Wg, int Kstride,
    const float* __restrict__ bg,
    const float* __restrict__ tW, float tval,
    const float* __restrict__ Ain, float* __restrict__ Aout,
    float* __restrict__ Ws,
    int K, int O, bool act, int tid)
{
    const int tx = tid & 15;        // col group: cols tx*4..tx*4+3
    const int ty = tid >> 4;        // row group: rows ty*4..ty*4+3
    const int o_l = ty;             // weight-load o lane (0..15)
    const int k_l = tx;             // weight-load k lane (0..15)

    for (int ot = 0; ot < O; ot += 64) {
        float acc[4][4] = {};
        float wreg[4];
        // prefetch first chunk of this column tile
        #pragma unroll
        for (int p = 0; p < 4; p++)
            wreg[p] = Wg[(size_t)(ot + o_l + p * 16) * Kstride + k_l];

        for (int kc = 0; kc < K; kc += KC) {
            __syncthreads();                    // prev readers of Ws done
            #pragma unroll
            for (int p = 0; p < 4; p++)
                Ws[k_l * WST + o_l + p * 16] = wreg[p];
            __syncthreads();                    // Ws chunk visible

            const int kn = kc + KC;
            if (kn < K) {                       // overlap next-chunk LDG with compute
                #pragma unroll
                for (int p = 0; p < 4; p++)
                    wreg[p] = Wg[(size_t)(ot + o_l + p * 16) * Kstride + kn + k_l];
            }

            #pragma unroll
            for (int k = 0; k < KC; k++) {
                float4 a = *(const float4*)(Ain + (kc + k) * AST + (ty << 2));
                float4 w = *(const float4*)(Ws + k * WST + (tx << 2));
                acc[0][0] += a.x * w.x; acc[0][1] += a.x * w.y;
                acc[0][2] += a.x * w.z; acc[0][3] += a.x * w.w;
                acc[1][0] += a.y * w.x; acc[1][1] += a.y * w.y;
                acc[1][2] += a.y * w.z; acc[1][3] += a.y * w.w;
                acc[2][0] += a.z * w.x; acc[2][1] += a.z * w.y;
                acc[2][2] += a.z * w.z; acc[2][3] += a.z * w.w;
                acc[3][0] += a.w * w.x; acc[3][1] += a.w * w.y;
                acc[3][2] += a.w * w.z; acc[3][3] += a.w * w.w;
            }
        }

        // epilogue: bias (+ folded time term), sin(30x), transpose-store to Aout[o][r]
        #pragma unroll
        for (int j = 0; j < 4; j++) {
            int o = ot + (tx << 2) + j;
            float bb = bg[o];
            if (tW) bb += tval * tW[(size_t)o * Kstride];
            float4 v;
            v.x = acc[0][j] + bb;
            v.y = acc[1][j] + bb;
            v.z = acc[2][j] + bb;
            v.w = acc[3][j] + bb;
            if (act) {
                v.x = __sinf(30.0f * v.x);
                v.y = __sinf(30.0f * v.y);
                v.z = __sinf(30.0f * v.z);
                v.w = __sinf(30.0f * v.w);
            }
            *(float4*)(Aout + o * AST + (ty << 2)) = v;
        }
    }
}

extern __shared__ float s_dyn[];

__global__ void __launch_bounds__(NTHR, 1)
siren_kernel(const float* __restrict__ feat,
             const float* __restrict__ times,
             P6 p,
             float* __restrict__ out)
{
    float* A0 = s_dyn;                    // [256][AST]
    float* A1 = s_dyn + 256 * AST;        // [256][AST]
    float* Ws = s_dyn + 2 * 256 * AST;    // [KC][WST]

    const int tid  = threadIdx.x;
    const int tile = blockIdx.x;          // 0..1919
    const int t    = blockIdx.y;          // 0..2
    const int bimg = tile / (HWSZ / 64);  // 0..1
    const int pix0 = (tile % (HWSZ / 64)) * 64;

    // Load 64x64 feat tile (identity gather): A0[c][r] = feat[b][c][pix0+r]
    const float* fb = feat + (size_t)bimg * 64 * HWSZ + pix0;
    #pragma unroll 4
    for (int i = tid; i < 64 * 64; i += NTHR) {
        int c = i >> 6, r = i & 63;
        A0[c * AST + r] = fb[(size_t)c * HWSZ + r];
    }
    const float tval = __ldg(times + t);

    // L0: 64(+t)->64 sin     (t column folded into bias)
    layer_gemm(p.w[0], 65,  p.b[0], p.w[0] + 64, tval, A0, A1, Ws,  64,  64, true,  tid);
    // L1: 64->64 sin
    layer_gemm(p.w[1], 64,  p.b[1], nullptr, 0.f,      A1, A0, Ws,  64,  64, true,  tid);
    // L2: 64->256 sin
    layer_gemm(p.w[2], 64,  p.b[2], nullptr, 0.f,      A0, A1, Ws,  64, 256, true,  tid);
    // L3: 256->256 sin
    layer_gemm(p.w[3], 256, p.b[3], nullptr, 0.f,      A1, A0, Ws, 256, 256, true,  tid);
    // L4: 256->256 sin
    layer_gemm(p.w[4], 256, p.b[4], nullptr, 0.f,      A0, A1, Ws, 256, 256, true,  tid);
    // L5: 256->64 linear
    layer_gemm(p.w[5], 256, p.b[5], nullptr, 0.f,      A1, A0, Ws, 256,  64, false, tid);

    __syncthreads();

    // Store: out[t][b][c][pix0+r] = A0[c][r]  (coalesced per channel row)
    float* ob = out + ((size_t)t * NBATCH + bimg) * 64 * HWSZ + pix0;
    #pragma unroll 4
    for (int i = tid; i < 64 * 64; i += NTHR) {
        int c = i >> 6, r = i & 63;
        ob[(size_t)c * HWSZ + r] = A0[c * AST + r];
    }
}

extern "C" void kernel_launch(void* const* d_in, const int* in_sizes, int n_in,
                              void* d_out, int out_size)
{
    const float* feat  = (const float*)d_in[0];
    const float* times = (const float*)d_in[1];
    P6 p;
    for (int i = 0; i < 6; i++) {
        p.w[i] = (const float*)d_in[2 + 2 * i];
        p.b[i] = (const float*)d_in[3 + 2 * i];
    }
    float* out = (float*)d_out;

    const int smem_bytes = (2 * 256 * AST + KC * WST) * (int)sizeof(float); // 143,616 B
    cudaFuncSetAttribute(siren_kernel, cudaFuncAttributeMaxDynamicSharedMemorySize,
                         smem_bytes);

    dim3 grid((NBATCH * HWSZ) / 64, 3);   // (1920, 3)
    siren_kernel<<<grid, NTHR, smem_bytes>>>(feat, times, p, out);
}